// round 15
// baseline (speedup 1.0000x reference)
#include <cuda_runtime.h>
#include <cuda_bf16.h>

// ---------------------------------------------------------------------------
// Forecaster_PONI round 15: R14 champion + (a) gate3 NCO 64->32 (grid 432->864,
// fixes measured grid starvation), (b) enc3 moved to the validated bf16 kernel
// via a STRIDE template param (stride-2, pad_lo=0). All else identical to R14.
// ---------------------------------------------------------------------------

__device__ __forceinline__ float lrelu_f(float v) { return v > 0.f ? v : 0.2f * v; }
__device__ __forceinline__ float sigm_f(float v)  { return 1.f / (1.f + __expf(-v)); }

__device__ __forceinline__ void mma16(float* d, const unsigned* a,
                                      unsigned b0, unsigned b1) {
    asm volatile(
        "mma.sync.aligned.m16n8k16.row.col.f32.bf16.bf16.f32 "
        "{%0,%1,%2,%3}, {%4,%5,%6,%7}, {%8,%9}, {%0,%1,%2,%3};"
        : "+f"(d[0]), "+f"(d[1]), "+f"(d[2]), "+f"(d[3])
        : "r"(a[0]), "r"(a[1]), "r"(a[2]), "r"(a[3]), "r"(b0), "r"(b1));
}

// ------------------------------ scratch buffers ----------------------------
__device__ float g_e1[160 * 16 * 96 * 96];
__device__ float g_e2[160 * 64 * 48 * 48];
__device__ float g_e3[160 * 96 * 24 * 24];
__device__ float g_c3[2][16 * 96 * 24 * 24];
__device__ float g_c2[2][16 * 64 * 48 * 48];
__device__ float g_c1[2][16 * 16 * 96 * 96];
__device__ float g_g3[16 * 192 * 24 * 24];
__device__ float g_g2[16 * 128 * 48 * 48];
__device__ float g_g1[16 * 32 * 96 * 96];
__device__ float g_o3[16 * 64 * 48 * 48];
__device__ float g_o2[16 * 16 * 96 * 96];
__device__ float g_o1[16 * 8 * 192 * 192];
__device__ float g_partD[2 * 16 * 64 * 48 * 48];

static const int NB = 16;  // batch

// ---------------------------------------------------------------------------
// bf16conv_k: 3x3 SAME conv over [x1 (C1) ++ x2 (C2)] as implicit GEMM.
// STRIDE 1: in[S*y+dy-1] (pad 1/1). STRIDE 2: in[2y+dy] (pad_lo=0, pad_hi=1).
// M = 64 px/block (output coords), N = NCO chans, K = CI*9 in tiles of 32,
// 3xBF16 hi/lo decomposition (fp32-level accuracy).
// MODE 1 = plain/gate conv. MODE 2 = candidate (x2 scaled by r on load;
// epilogue GRU combine). ACT: 1 lrelu, 2 sigmoid.
// ---------------------------------------------------------------------------
template<int C1, int C2, int CO, int H, int W, int NCO, int MT, int MODE, int ACT,
         int STRIDE>
__global__ void __launch_bounds__(128)
bf16conv_k(const float* __restrict__ x1, const float* __restrict__ x2,
           const float* __restrict__ gates, const float* __restrict__ wgt,
           const float* __restrict__ bias, float* __restrict__ out)
{
    constexpr int CI   = C1 + C2;
    constexpr int K    = CI * 9;
    constexpr int KT   = 32, KTP = 34;
    constexpr int MBLK = 64 * MT;
    constexpr int NT8  = NCO / 8;
    constexpr int HIN  = H * STRIDE, WIN = W * STRIDE;
    constexpr int OFF  = (STRIDE == 1) ? 1 : 0;

    __shared__ __nv_bfloat16 sAh[MBLK][KTP], sAl[MBLK][KTP];
    __shared__ __nv_bfloat16 sBh[NCO][KTP],  sBl[NCO][KTP];

    const int n    = blockIdx.z;
    const int cob  = blockIdx.y * NCO;
    const int tile = blockIdx.x;
    const int tid  = threadIdx.x;
    const int wid  = tid >> 5;
    const int lane = tid & 31;
    const int gid  = lane >> 2;
    const int tig  = lane & 3;

    float acc[MT][NT8][4];
#pragma unroll
    for (int mt = 0; mt < MT; mt++)
#pragma unroll
        for (int j = 0; j < NT8; j++)
#pragma unroll
            for (int e = 0; e < 4; e++) acc[mt][j][e] = 0.f;

    for (int k0 = 0; k0 < K; k0 += KT) {
#pragma unroll
        for (int i = 0; i < MBLK * KT / 128; i++) {
            int idx = tid + i * 128;
            int kk  = idx & 31;
            int m   = idx >> 5;
            int k   = k0 + kk;
            int ci  = k / 9;
            int t   = k - 9 * ci;
            int dy  = t / 3, dx = t - 3 * dy;
            int p   = tile * MBLK + m;
            int y   = p / W, x = p - y * W;
            int gy  = STRIDE * y + dy - OFF, gx = STRIDE * x + dx - OFF;
            float v = 0.f;
            if ((unsigned)gy < (unsigned)HIN && (unsigned)gx < (unsigned)WIN) {
                if (ci < C1) {
                    v = x1[(((size_t)n * C1 + ci) * HIN + gy) * WIN + gx];
                } else {
                    int c2 = ci - C1;
                    v = x2[(((size_t)n * C2 + c2) * HIN + gy) * WIN + gx];
                    if (MODE == 2)
                        v *= gates[(((size_t)n * 2 * C2 + C2 + c2) * HIN + gy) * WIN + gx];
                }
            }
            __nv_bfloat16 h = __float2bfloat16(v);
            sAh[m][kk] = h;
            sAl[m][kk] = __float2bfloat16(v - __bfloat162float(h));
        }
#pragma unroll
        for (int i = 0; i < (NCO * KT + 127) / 128; i++) {
            int idx = tid + i * 128;
            if (idx < NCO * KT) {
                int kk = idx & 31;
                int co = idx >> 5;
                int k  = k0 + kk;
                int ci = k / 9;
                int t  = k - 9 * ci;
                float v = wgt[((size_t)(cob + co) * CI + ci) * 9 + t];
                __nv_bfloat16 h = __float2bfloat16(v);
                sBh[co][kk] = h;
                sBl[co][kk] = __float2bfloat16(v - __bfloat162float(h));
            }
        }
        __syncthreads();

#pragma unroll
        for (int c = 0; c < 2; c++) {
            const int ck = 16 * c;
            unsigned ah[MT][4], al[MT][4];
#pragma unroll
            for (int mt = 0; mt < MT; mt++) {
                int r0 = wid * 16 * MT + 16 * mt;
                ah[mt][0] = *(const unsigned*)&sAh[r0 + gid][ck + 2 * tig];
                ah[mt][1] = *(const unsigned*)&sAh[r0 + gid + 8][ck + 2 * tig];
                ah[mt][2] = *(const unsigned*)&sAh[r0 + gid][ck + 2 * tig + 8];
                ah[mt][3] = *(const unsigned*)&sAh[r0 + gid + 8][ck + 2 * tig + 8];
                al[mt][0] = *(const unsigned*)&sAl[r0 + gid][ck + 2 * tig];
                al[mt][1] = *(const unsigned*)&sAl[r0 + gid + 8][ck + 2 * tig];
                al[mt][2] = *(const unsigned*)&sAl[r0 + gid][ck + 2 * tig + 8];
                al[mt][3] = *(const unsigned*)&sAl[r0 + gid + 8][ck + 2 * tig + 8];
            }
#pragma unroll
            for (int j = 0; j < NT8; j++) {
                int col = 8 * j + gid;
                unsigned bh0 = *(const unsigned*)&sBh[col][ck + 2 * tig];
                unsigned bh1 = *(const unsigned*)&sBh[col][ck + 2 * tig + 8];
                unsigned bl0 = *(const unsigned*)&sBl[col][ck + 2 * tig];
                unsigned bl1 = *(const unsigned*)&sBl[col][ck + 2 * tig + 8];
#pragma unroll
                for (int mt = 0; mt < MT; mt++) {
                    mma16(acc[mt][j], ah[mt], bh0, bh1);
                    mma16(acc[mt][j], ah[mt], bl0, bl1);
                    mma16(acc[mt][j], al[mt], bh0, bh1);
                }
            }
        }
        __syncthreads();
    }

#pragma unroll
    for (int mt = 0; mt < MT; mt++) {
#pragma unroll
        for (int j = 0; j < NT8; j++) {
#pragma unroll
            for (int e = 0; e < 4; e++) {
                int r  = wid * 16 * MT + 16 * mt + gid + ((e >> 1) ? 8 : 0);
                int cc = 8 * j + 2 * tig + (e & 1);
                int p  = tile * MBLK + r;
                int y  = p / W, x = p - y * W;
                int co = cob + cc;
                float v = acc[mt][j][e] + bias[co];
                if (ACT == 1) v = lrelu_f(v);
                if (ACT == 2) v = sigm_f(v);
                size_t off = (((size_t)n * CO + co) * H + y) * W + x;
                if (MODE == 2) {
                    float z = gates[(((size_t)n * 2 * CO + co) * H + y) * W + x];
                    float h = x2[off];
                    v = (1.f - z) * h + z * v;
                }
                out[off] = v;
            }
        }
    }
}

// ---------------------------------------------------------------------------
// R2 deconv (L3): 2x2 input px -> 4x4 outputs; FUSE=0 -> raw partial write.
// ---------------------------------------------------------------------------
template<int CI, int CO, int HIN, int TY, int TX, int CICH, int COT, int SPLIT, int FUSE>
__global__ void __launch_bounds__((TY / 2) * (TX / 2))
deconv_v2(const float* __restrict__ x, const float* __restrict__ wgt,
          const float* __restrict__ bias, float* __restrict__ out)
{
    constexpr int WIN = HIN, HO = 2 * HIN, WO = 2 * HIN;
    constexpr int CIP = CI / SPLIT;
    constexpr int SH  = TY + 2, SW = TX + 2, SWP = (SW + 3) & ~3;
    constexpr int NT  = (TY / 2) * (TX / 2);
    constexpr int TILES_X = WIN / TX;

    __shared__ __align__(16) float s_in[CICH][SH][SWP];
    __shared__ __align__(16) float s_w[CICH][COT][16];

    const int zs  = blockIdx.z;
    const int n   = zs / SPLIT;
    const int sp  = zs % SPLIT;
    const int cob = blockIdx.y * COT;
    const int ty0 = (blockIdx.x / TILES_X) * TY;
    const int tx0 = (blockIdx.x % TILES_X) * TX;
    const int tid = threadIdx.x;
    const int lx  = tid % (TX / 2);
    const int ly  = tid / (TX / 2);

    float acc[COT][4][4];
#pragma unroll
    for (int c = 0; c < COT; c++)
#pragma unroll
        for (int u = 0; u < 4; u++)
#pragma unroll
            for (int v = 0; v < 4; v++) acc[c][u][v] = 0.f;

    const int ci_base = sp * CIP;
    for (int ci0 = 0; ci0 < CIP; ci0 += CICH) {
        for (int idx = tid; idx < CICH * SH * SW; idx += NT) {
            int c   = idx / (SH * SW);
            int rem = idx - c * (SH * SW);
            int iy  = rem / SW;
            int ix  = rem - iy * SW;
            int gy = ty0 + iy - 1, gx = tx0 + ix - 1;
            float v = 0.f;
            if ((unsigned)gy < (unsigned)HIN && (unsigned)gx < (unsigned)WIN)
                v = x[(((size_t)n * CI + (ci_base + ci0 + c)) * HIN + gy) * WIN + gx];
            s_in[c][iy][ix] = v;
        }
        for (int idx = tid; idx < CICH * COT * 16; idx += NT) {
            int c   = idx / (COT * 16);
            int rem = idx - c * (COT * 16);
            int co  = rem / 16;
            int k   = rem - co * 16;
            s_w[c][co][k] = wgt[((cob + co) * CI + (ci_base + ci0 + c)) * 16 + k];
        }
        __syncthreads();

#pragma unroll
        for (int c = 0; c < CICH; c++) {
            float p[4][4];
#pragma unroll
            for (int r = 0; r < 4; r++) {
                float2 a = *(const float2*)&s_in[c][2 * ly + r][2 * lx];
                float2 b = *(const float2*)&s_in[c][2 * ly + r][2 * lx + 2];
                p[r][0] = a.x; p[r][1] = a.y; p[r][2] = b.x; p[r][3] = b.y;
            }
#pragma unroll
            for (int co = 0; co < COT; co++) {
                float wk[16];
#pragma unroll
                for (int q = 0; q < 4; q++) {
                    float4 wv = *(const float4*)&s_w[c][co][4 * q];
                    wk[4 * q] = wv.x; wk[4 * q + 1] = wv.y;
                    wk[4 * q + 2] = wv.z; wk[4 * q + 3] = wv.w;
                }
#pragma unroll
                for (int u = 0; u < 4; u++)
#pragma unroll
                    for (int v = 0; v < 4; v++)
#pragma unroll
                        for (int a = 0; a < 2; a++)
#pragma unroll
                            for (int b = 0; b < 2; b++)
                                acc[co][u][v] = fmaf(
                                    p[(u >> 1) + (u & 1) + a][(v >> 1) + (v & 1) + b],
                                    wk[((u & 1) + 2 * a) * 4 + (v & 1) + 2 * b],
                                    acc[co][u][v]);
            }
        }
        __syncthreads();
    }

    const int orow0 = 2 * ty0 + 4 * ly;
    const int ocol0 = 2 * tx0 + 4 * lx;
#pragma unroll
    for (int co = 0; co < COT; co++) {
        float bv = FUSE ? bias[cob + co] : 0.f;
#pragma unroll
        for (int u = 0; u < 4; u++) {
            float4 v;
            if (FUSE) {
                v.x = lrelu_f(acc[co][u][0] + bv);
                v.y = lrelu_f(acc[co][u][1] + bv);
                v.z = lrelu_f(acc[co][u][2] + bv);
                v.w = lrelu_f(acc[co][u][3] + bv);
                *(float4*)&out[(((size_t)n * CO + cob + co) * HO + orow0 + u) * WO + ocol0] = v;
            } else {
                v.x = acc[co][u][0]; v.y = acc[co][u][1];
                v.z = acc[co][u][2]; v.w = acc[co][u][3];
                *(float4*)&out[(((size_t)(sp * NB + n) * CO + cob + co) * HO + orow0 + u) * WO + ocol0] = v;
            }
        }
    }
}

// ---------------------------------------------------------------------------
// Epilogue: sum SPLIT partials + bias; MODE 0 lrelu.
// ---------------------------------------------------------------------------
template<int CO, int HW, int SPLIT, int MODE>
__global__ void epi_k(const float* __restrict__ part, const float* __restrict__ bias,
                      const float* __restrict__ gates, const float* __restrict__ hprev,
                      float* __restrict__ out)
{
    constexpr size_t TOT = (size_t)NB * CO * HW;
    size_t i = ((size_t)blockIdx.x * blockDim.x + threadIdx.x) * 4;
    if (i >= TOT) return;
    int c   = (int)((i / HW) % CO);
    float4 s = *(const float4*)&part[i];
#pragma unroll
    for (int sp = 1; sp < SPLIT; sp++) {
        float4 q = *(const float4*)&part[(size_t)sp * TOT + i];
        s.x += q.x; s.y += q.y; s.z += q.z; s.w += q.w;
    }
    float bv = bias[c];
    s.x += bv; s.y += bv; s.z += bv; s.w += bv;
    if (MODE == 0) {
        s.x = lrelu_f(s.x); s.y = lrelu_f(s.y); s.z = lrelu_f(s.z); s.w = lrelu_f(s.w);
    } else if (MODE == 1) {
        s.x = sigm_f(s.x); s.y = sigm_f(s.y); s.z = sigm_f(s.z); s.w = sigm_f(s.w);
    } else {
        int n   = (int)(i / ((size_t)HW * CO));
        size_t pix = i % HW;
        float4 z = *(const float4*)&gates[((size_t)(n * 2 * CO + c)) * HW + pix];
        float4 h = *(const float4*)&hprev[i];
        s.x = (1.f - z.x) * h.x + z.x * lrelu_f(s.x);
        s.y = (1.f - z.y) * h.y + z.y * lrelu_f(s.y);
        s.z = (1.f - z.z) * h.z + z.z * lrelu_f(s.z);
        s.w = (1.f - z.w) * h.w + z.w * lrelu_f(s.w);
    }
    *(float4*)&out[i] = s;
}

// ---------------------------------------------------------------------------
// R1 conv3x3 (L2/L1): 2x2 px x COT per thread — measured-faster fp32 path.
// ---------------------------------------------------------------------------
template<int C1, int C2, int CO, int H, int W, int ACT, int MODE,
         int TY, int TX, int CICH, int COT>
__global__ void __launch_bounds__((TY / 2) * (TX / 2))
conv3x3_k(const float* __restrict__ x1, const float* __restrict__ x2,
          const float* __restrict__ gates, const float* __restrict__ wgt,
          const float* __restrict__ bias, float* __restrict__ out)
{
    constexpr int CI = C1 + C2;
    constexpr int SH = TY + 2, SW = TX + 2;
    constexpr int NT = (TY / 2) * (TX / 2);
    constexpr int TILES_X = (W + TX - 1) / TX;
    __shared__ float s_in[CICH][SH][SW];
    __shared__ float s_w[CICH][COT][9];

    const int n   = blockIdx.z;
    const int cob = blockIdx.y * COT;
    const int ty0 = (blockIdx.x / TILES_X) * TY;
    const int tx0 = (blockIdx.x % TILES_X) * TX;
    const int tid = threadIdx.x;
    const int lx  = tid % (TX / 2);
    const int ly  = tid / (TX / 2);

    float acc[COT][2][2];
#pragma unroll
    for (int c = 0; c < COT; c++) {
        acc[c][0][0] = acc[c][0][1] = acc[c][1][0] = acc[c][1][1] = 0.f;
    }

    for (int ci0 = 0; ci0 < CI; ci0 += CICH) {
        for (int idx = tid; idx < CICH * SH * SW; idx += NT) {
            int c   = idx / (SH * SW);
            int rem = idx - c * (SH * SW);
            int iy  = rem / SW;
            int ix  = rem - iy * SW;
            int gy = ty0 + iy - 1, gx = tx0 + ix - 1;
            int ci = ci0 + c;
            float v = 0.f;
            if ((unsigned)gy < (unsigned)H && (unsigned)gx < (unsigned)W) {
                if (ci < C1) {
                    v = x1[(((size_t)n * C1 + ci) * H + gy) * W + gx];
                } else {
                    int c2 = ci - C1;
                    v = x2[(((size_t)n * C2 + c2) * H + gy) * W + gx];
                    if (MODE == 2)
                        v *= gates[(((size_t)n * 2 * C2 + C2 + c2) * H + gy) * W + gx];
                }
            }
            s_in[c][iy][ix] = v;
        }
        for (int idx = tid; idx < CICH * COT * 9; idx += NT) {
            int c   = idx / (COT * 9);
            int rem = idx - c * (COT * 9);
            int co  = rem / 9;
            int k   = rem - co * 9;
            s_w[c][co][k] = wgt[((cob + co) * CI + (ci0 + c)) * 9 + k];
        }
        __syncthreads();

        for (int c = 0; c < CICH; c++) {
            float p[4][4];
#pragma unroll
            for (int i = 0; i < 4; i++)
#pragma unroll
                for (int j = 0; j < 4; j++)
                    p[i][j] = s_in[c][2 * ly + i][2 * lx + j];
#pragma unroll
            for (int co = 0; co < COT; co++) {
#pragma unroll
                for (int ky = 0; ky < 3; ky++)
#pragma unroll
                    for (int kx = 0; kx < 3; kx++) {
                        float wv = s_w[c][co][ky * 3 + kx];
                        acc[co][0][0] = fmaf(p[ky][kx],         wv, acc[co][0][0]);
                        acc[co][0][1] = fmaf(p[ky][kx + 1],     wv, acc[co][0][1]);
                        acc[co][1][0] = fmaf(p[ky + 1][kx],     wv, acc[co][1][0]);
                        acc[co][1][1] = fmaf(p[ky + 1][kx + 1], wv, acc[co][1][1]);
                    }
            }
        }
        __syncthreads();
    }

    const int oy = ty0 + 2 * ly, ox = tx0 + 2 * lx;
#pragma unroll
    for (int co = 0; co < COT; co++) {
        float bv = bias[cob + co];
#pragma unroll
        for (int i = 0; i < 2; i++)
#pragma unroll
            for (int j = 0; j < 2; j++) {
                int y = oy + i, x = ox + j;
                if (y < H && x < W) {
                    float v = acc[co][i][j] + bv;
                    if (ACT == 1) v = lrelu_f(v);
                    if (ACT == 2) v = sigm_f(v);
                    size_t off = (((size_t)n * CO + cob + co) * H + y) * W + x;
                    if (MODE == 2) {
                        float z = gates[(((size_t)n * 2 * CO + cob + co) * H + y) * W + x];
                        float h = x2[off];
                        v = (1.f - z) * h + z * v;
                    }
                    out[off] = v;
                }
            }
    }
}

// ---------------------------------------------------------------------------
// R1 deconv (L2/L1): fused lrelu.
// ---------------------------------------------------------------------------
template<int CI, int CO, int HIN, int TY, int TX, int CICH, int COT>
__global__ void __launch_bounds__(TY * TX)
deconv4x4_k(const float* __restrict__ x, const float* __restrict__ wgt,
            const float* __restrict__ bias, float* __restrict__ out)
{
    constexpr int WIN = HIN, HO = 2 * HIN, WO = 2 * HIN;
    constexpr int SH = TY + 2, SW = TX + 2;
    constexpr int NT = TY * TX;
    constexpr int TILES_X = (WIN + TX - 1) / TX;
    __shared__ float s_in[CICH][SH][SW];
    __shared__ float s_w[CICH][COT][16];

    const int n   = blockIdx.z;
    const int cob = blockIdx.y * COT;
    const int ty0 = (blockIdx.x / TILES_X) * TY;
    const int tx0 = (blockIdx.x % TILES_X) * TX;
    const int tid = threadIdx.x;
    const int lx  = tid % TX;
    const int ly  = tid / TX;

    float acc[COT][2][2];
#pragma unroll
    for (int c = 0; c < COT; c++) {
        acc[c][0][0] = acc[c][0][1] = acc[c][1][0] = acc[c][1][1] = 0.f;
    }

    for (int ci0 = 0; ci0 < CI; ci0 += CICH) {
        for (int idx = tid; idx < CICH * SH * SW; idx += NT) {
            int c   = idx / (SH * SW);
            int rem = idx - c * (SH * SW);
            int iy  = rem / SW;
            int ix  = rem - iy * SW;
            int gy = ty0 + iy - 1, gx = tx0 + ix - 1;
            float v = 0.f;
            if ((unsigned)gy < (unsigned)HIN && (unsigned)gx < (unsigned)WIN)
                v = x[(((size_t)n * CI + (ci0 + c)) * HIN + gy) * WIN + gx];
            s_in[c][iy][ix] = v;
        }
        for (int idx = tid; idx < CICH * COT * 16; idx += NT) {
            int c   = idx / (COT * 16);
            int rem = idx - c * (COT * 16);
            int co  = rem / 16;
            int k   = rem - co * 16;
            s_w[c][co][k] = wgt[((cob + co) * CI + (ci0 + c)) * 16 + k];
        }
        __syncthreads();

        for (int c = 0; c < CICH; c++) {
            float p[3][3];
#pragma unroll
            for (int r = 0; r < 3; r++)
#pragma unroll
                for (int cc = 0; cc < 3; cc++)
                    p[r][cc] = s_in[c][ly + r][lx + cc];
#pragma unroll
            for (int co = 0; co < COT; co++) {
#pragma unroll
                for (int dy = 0; dy < 2; dy++)
#pragma unroll
                    for (int dx = 0; dx < 2; dx++)
#pragma unroll
                        for (int a = 0; a < 2; a++)
#pragma unroll
                            for (int b = 0; b < 2; b++)
                                acc[co][dy][dx] =
                                    fmaf(p[a + dy][b + dx],
                                         s_w[c][co][(dy + 2 * a) * 4 + (dx + 2 * b)],
                                         acc[co][dy][dx]);
            }
        }
        __syncthreads();
    }

    const int iy = ty0 + ly, ix = tx0 + lx;
    if (iy < HIN && ix < WIN) {
#pragma unroll
        for (int co = 0; co < COT; co++) {
            float bv = bias[cob + co];
#pragma unroll
            for (int dy = 0; dy < 2; dy++)
#pragma unroll
                for (int dx = 0; dx < 2; dx++) {
                    float v = lrelu_f(acc[co][dy][dx] + bv);
                    out[(((size_t)n * CO + cob + co) * HO + 2 * iy + dy) * WO + 2 * ix + dx] = v;
                }
        }
    }
}

// ---------------------------------------------------------------------------
// Encoder: 3x3 stride-2 SAME conv (enc1/enc2). REMAP folds [B,T]->[T,B].
// ---------------------------------------------------------------------------
template<int CI, int CO, int HIN, bool REMAP, int TY, int TX, int CICH, int COT>
__global__ void __launch_bounds__(TY * TX)
conv3x3s2_k(const float* __restrict__ x, const float* __restrict__ wgt,
            const float* __restrict__ bias, float* __restrict__ out)
{
    constexpr int WIN = HIN, HO = HIN / 2, WO = HIN / 2;
    constexpr int SH = 2 * TY + 1, SW = 2 * TX + 1;
    constexpr int NT = TY * TX;
    constexpr int TILES_X = (WO + TX - 1) / TX;
    __shared__ float s_in[CICH][SH][SW];
    __shared__ float s_w[CICH][COT][9];

    const int n   = blockIdx.z;
    const int cob = blockIdx.y * COT;
    const int ty0 = (blockIdx.x / TILES_X) * TY;
    const int tx0 = (blockIdx.x % TILES_X) * TX;
    const int tid = threadIdx.x;
    const int lx  = tid % TX;
    const int ly  = tid / TX;

    float acc[COT];
#pragma unroll
    for (int c = 0; c < COT; c++) acc[c] = 0.f;

    for (int ci0 = 0; ci0 < CI; ci0 += CICH) {
        for (int idx = tid; idx < CICH * SH * SW; idx += NT) {
            int c   = idx / (SH * SW);
            int rem = idx - c * (SH * SW);
            int iy  = rem / SW;
            int ix  = rem - iy * SW;
            int gy = 2 * ty0 + iy, gx = 2 * tx0 + ix;
            int ci = ci0 + c;
            float v = 0.f;
            if (gy < HIN && gx < WIN) {
                int frame = REMAP ? ((n % 16) * 10 + n / 16) : n;
                v = x[(((size_t)frame * CI + ci) * HIN + gy) * WIN + gx];
            }
            s_in[c][iy][ix] = v;
        }
        for (int idx = tid; idx < CICH * COT * 9; idx += NT) {
            int c   = idx / (COT * 9);
            int rem = idx - c * (COT * 9);
            int co  = rem / 9;
            int k   = rem - co * 9;
            s_w[c][co][k] = wgt[((cob + co) * CI + (ci0 + c)) * 9 + k];
        }
        __syncthreads();

        for (int c = 0; c < CICH; c++) {
            float p[3][3];
#pragma unroll
            for (int r = 0; r < 3; r++)
#pragma unroll
                for (int cc = 0; cc < 3; cc++)
                    p[r][cc] = s_in[c][2 * ly + r][2 * lx + cc];
#pragma unroll
            for (int co = 0; co < COT; co++) {
#pragma unroll
                for (int k = 0; k < 9; k++)
                    acc[co] = fmaf(p[k / 3][k % 3], s_w[c][co][k], acc[co]);
            }
        }
        __syncthreads();
    }

    const int oy = ty0 + ly, ox = tx0 + lx;
    if (oy < HO && ox < WO) {
#pragma unroll
        for (int co = 0; co < COT; co++) {
            float v = lrelu_f(acc[co] + bias[cob + co]);
            out[(((size_t)n * CO + cob + co) * HO + oy) * WO + ox] = v;
        }
    }
}

// ---------------------------------------------------------------------------
// Head: 3x3 conv, 8 -> 1 channels, 192x192.
// ---------------------------------------------------------------------------
__global__ void head_k(const float* __restrict__ x, const float* __restrict__ w,
                       const float* __restrict__ b, float* __restrict__ out)
{
    __shared__ float sw[72];
    __shared__ float sb;
    if (threadIdx.x < 72) sw[threadIdx.x] = w[threadIdx.x];
    if (threadIdx.x == 0) sb = b[0];
    __syncthreads();

    const int HW = 192 * 192;
    int idx = blockIdx.x * blockDim.x + threadIdx.x;
    if (idx >= 16 * HW) return;
    int n   = idx / HW;
    int rem = idx - n * HW;
    int y   = rem / 192;
    int xq  = rem - y * 192;

    float acc = sb;
#pragma unroll
    for (int ci = 0; ci < 8; ci++) {
        const float* xp = x + (size_t)(n * 8 + ci) * HW;
#pragma unroll
        for (int ky = 0; ky < 3; ky++) {
            int yy = y + ky - 1;
            if ((unsigned)yy >= 192u) continue;
#pragma unroll
            for (int kx = 0; kx < 3; kx++) {
                int xx = xq + kx - 1;
                if ((unsigned)xx >= 192u) continue;
                acc = fmaf(xp[yy * 192 + xx], sw[ci * 9 + ky * 3 + kx], acc);
            }
        }
    }
    out[idx] = acc;
}

// ---------------------------------------------------------------------------
// stream/event context — identical object count to the passing R8/R10 ctx.
// ---------------------------------------------------------------------------
struct PipeCtx {
    cudaStream_t sA, sB, sC;
    cudaEvent_t  fork, jA, jB, jC;
    cudaEvent_t  eA[10];    // A: c3n(t) ready
    cudaEvent_t  eBc3[10];  // B: deconv3(t) done reading c3n(t)
    cudaEvent_t  eB[10];    // B: c2n(t) ready
    cudaEvent_t  eCc2[10];  // C: deconv2(t) done reading c2n(t)
};

static PipeCtx* get_ctx() {
    static PipeCtx* c = nullptr;
    if (!c) {
        c = new PipeCtx;
        cudaStreamCreateWithFlags(&c->sA, cudaStreamNonBlocking);
        cudaStreamCreateWithFlags(&c->sB, cudaStreamNonBlocking);
        cudaStreamCreateWithFlags(&c->sC, cudaStreamNonBlocking);
        cudaEventCreateWithFlags(&c->fork, cudaEventDisableTiming);
        cudaEventCreateWithFlags(&c->jA,   cudaEventDisableTiming);
        cudaEventCreateWithFlags(&c->jB,   cudaEventDisableTiming);
        cudaEventCreateWithFlags(&c->jC,   cudaEventDisableTiming);
        for (int t = 0; t < 10; t++) {
            cudaEventCreateWithFlags(&c->eA[t],   cudaEventDisableTiming);
            cudaEventCreateWithFlags(&c->eBc3[t], cudaEventDisableTiming);
            cudaEventCreateWithFlags(&c->eB[t],   cudaEventDisableTiming);
            cudaEventCreateWithFlags(&c->eCc2[t], cudaEventDisableTiming);
        }
    }
    return c;
}

// ---------------------------------------------------------------------------
// host
// ---------------------------------------------------------------------------
extern "C" void kernel_launch(void* const* d_in, const int* in_sizes, int n_in,
                              void* d_out, int out_size)
{
    const float* h1     = (const float*)d_in[0];
    const float* h2     = (const float*)d_in[1];
    const float* h3     = (const float*)d_in[2];
    const float* y_add  = (const float*)d_in[3];
    const float* enc_w1 = (const float*)d_in[4];
    const float* enc_b1 = (const float*)d_in[5];
    const float* enc_w2 = (const float*)d_in[6];
    const float* enc_b2 = (const float*)d_in[7];
    const float* enc_w3 = (const float*)d_in[8];
    const float* enc_b3 = (const float*)d_in[9];
    const float* g3wg   = (const float*)d_in[10];
    const float* g3bg   = (const float*)d_in[11];
    const float* g3wc   = (const float*)d_in[12];
    const float* g3bc   = (const float*)d_in[13];
    const float* g2wg   = (const float*)d_in[14];
    const float* g2bg   = (const float*)d_in[15];
    const float* g2wc   = (const float*)d_in[16];
    const float* g2bc   = (const float*)d_in[17];
    const float* g1wg   = (const float*)d_in[18];
    const float* g1bg   = (const float*)d_in[19];
    const float* g1wc   = (const float*)d_in[20];
    const float* g1bc   = (const float*)d_in[21];
    const float* s3w    = (const float*)d_in[22];
    const float* s3b    = (const float*)d_in[23];
    const float* s2w    = (const float*)d_in[24];
    const float* s2b    = (const float*)d_in[25];
    const float* s1w    = (const float*)d_in[26];
    const float* s1b    = (const float*)d_in[27];
    const float* hw     = (const float*)d_in[28];
    const float* hb     = (const float*)d_in[29];
    float* out = (float*)d_out;

    float *e1, *e2, *e3, *c3b, *c2b, *c1b, *gg3, *gg2, *gg1, *o3, *o2, *o1, *partD;
    cudaGetSymbolAddress((void**)&e1, g_e1);
    cudaGetSymbolAddress((void**)&e2, g_e2);
    cudaGetSymbolAddress((void**)&e3, g_e3);
    cudaGetSymbolAddress((void**)&c3b, g_c3);
    cudaGetSymbolAddress((void**)&c2b, g_c2);
    cudaGetSymbolAddress((void**)&c1b, g_c1);
    cudaGetSymbolAddress((void**)&gg3, g_g3);
    cudaGetSymbolAddress((void**)&gg2, g_g2);
    cudaGetSymbolAddress((void**)&gg1, g_g1);
    cudaGetSymbolAddress((void**)&o3, g_o3);
    cudaGetSymbolAddress((void**)&o2, g_o2);
    cudaGetSymbolAddress((void**)&o1, g_o1);
    cudaGetSymbolAddress((void**)&partD, g_partD);

    PipeCtx* c = get_ctx();
    cudaStream_t sA = c->sA, sB = c->sB, sC = c->sC;

    const size_t SZ3 = (size_t)16 * 96 * 24 * 24;
    const size_t SZ2 = (size_t)16 * 64 * 48 * 48;
    const size_t SZ1 = (size_t)16 * 16 * 96 * 96;

    // -------- encoder on the capture-origin stream --------------------------
    conv3x3s2_k<1, 16, 192, true, 16, 16, 1, 16><<<dim3(36, 1, 160), 256>>>(
        y_add, enc_w1, enc_b1, e1);
    conv3x3s2_k<16, 64, 96, false, 16, 16, 8, 8><<<dim3(9, 8, 160), 256>>>(
        e1, enc_w2, enc_b2, e2);
    // enc3 on tensor cores: stride-2 bf16 implicit GEMM (K=576, grid 4320)
    bf16conv_k<64, 0, 96, 24, 24, 32, 1, 1, 1, 2>
        <<<dim3(9, 3, 160), 128>>>(e2, e2, nullptr, enc_w3, enc_b3, e3);

    cudaMemcpyAsync(c3b, h3, SZ3 * sizeof(float), cudaMemcpyDeviceToDevice);
    cudaMemcpyAsync(c2b, h2, SZ2 * sizeof(float), cudaMemcpyDeviceToDevice);
    cudaMemcpyAsync(c1b, h1, SZ1 * sizeof(float), cudaMemcpyDeviceToDevice);

    // -------- fork into 3 pipeline streams ----------------------------------
    cudaEventRecord(c->fork, 0);
    cudaStreamWaitEvent(sA, c->fork, 0);
    cudaStreamWaitEvent(sB, c->fork, 0);
    cudaStreamWaitEvent(sC, c->fork, 0);

    for (int t = 0; t < 10; t++) {
        const float* x3 = e3 + (size_t)t * 16 * 96 * 24 * 24;
        float* c3c = c3b + (size_t)(t & 1) * SZ3;
        float* c3n = c3b + (size_t)((t + 1) & 1) * SZ3;
        float* c2c = c2b + (size_t)(t & 1) * SZ2;
        float* c2n = c2b + (size_t)((t + 1) & 1) * SZ2;
        float* c1c = c1b + (size_t)(t & 1) * SZ1;
        float* c1n = c1b + (size_t)((t + 1) & 1) * SZ1;

        // ===== stream A: L3 GRU recurrence (bf16 tensor cores, fused) =====
        bf16conv_k<96, 96, 192, 24, 24, 32, 1, 1, 2, 1>
            <<<dim3(9, 6, 16), 128, 0, sA>>>(x3, c3c, nullptr, g3wg, g3bg, gg3);
        if (t >= 2) cudaStreamWaitEvent(sA, c->eBc3[t - 2], 0);
        bf16conv_k<96, 96, 96, 24, 24, 32, 1, 2, 1, 1>
            <<<dim3(9, 3, 16), 128, 0, sA>>>(x3, c3c, gg3, g3wc, g3bc, c3n);
        cudaEventRecord(c->eA[t], sA);                           // c3n(t) ready

        // ===== stream B: deconv3 -> o3, then L2 GRU (fp32, R10 configs) =====
        cudaStreamWaitEvent(sB, c->eA[t], 0);
        deconv_v2<96, 64, 24, 24, 24, 8, 4, 2, 0>
            <<<dim3(1, 16, 32), 144, 0, sB>>>(c3n, s3w, s3b, partD);
        cudaEventRecord(c->eBc3[t], sB);                         // done reading c3n(t)
        epi_k<64, 2304, 2, 0><<<2304, 256, 0, sB>>>(partD, s3b, nullptr, nullptr, o3);
        conv3x3_k<64, 64, 128, 48, 48, 2, 1, 16, 48, 8, 8>
            <<<dim3(3, 16, 16), 192, 0, sB>>>(o3, c2c, nullptr, g2wg, g2bg, gg2);
        if (t >= 2) cudaStreamWaitEvent(sB, c->eCc2[t - 2], 0);
        conv3x3_k<64, 64, 64, 48, 48, 1, 2, 16, 48, 8, 8>
            <<<dim3(3, 8, 16), 192, 0, sB>>>(o3, c2c, gg2, g2wc, g2bc, c2n);
        cudaEventRecord(c->eB[t], sB);                           // c2n(t) ready

        // ===== stream C: deconv2 -> o2, L1 GRU (fp32), deconv1, head =====
        cudaStreamWaitEvent(sC, c->eB[t], 0);
        deconv4x4_k<64, 16, 48, 16, 48, 8, 4>
            <<<dim3(3, 4, 16), 768, 0, sC>>>(c2n, s2w, s2b, o2);
        cudaEventRecord(c->eCc2[t], sC);                         // done reading c2n(t)
        conv3x3_k<16, 16, 32, 96, 96, 2, 1, 16, 48, 8, 8>
            <<<dim3(12, 4, 16), 192, 0, sC>>>(o2, c1c, nullptr, g1wg, g1bg, gg1);
        conv3x3_k<16, 16, 16, 96, 96, 1, 2, 16, 48, 8, 8>
            <<<dim3(12, 2, 16), 192, 0, sC>>>(o2, c1c, gg1, g1wc, g1bc, c1n);
        deconv4x4_k<16, 8, 96, 16, 48, 8, 8>
            <<<dim3(12, 1, 16), 768, 0, sC>>>(c1n, s1w, s1b, o1);
        head_k<<<dim3((16 * 192 * 192 + 255) / 256), 256, 0, sC>>>(
            o1, hw, hb, out + (size_t)t * 16 * 192 * 192);
    }

    // -------- join all streams back to the capture-origin stream ------------
    cudaEventRecord(c->jA, sA);
    cudaEventRecord(c->jB, sB);
    cudaEventRecord(c->jC, sC);
    cudaStreamWaitEvent(0, c->jA, 0);
    cudaStreamWaitEvent(0, c->jB, 0);
    cudaStreamWaitEvent(0, c->jC, 0);
}

// round 16
// speedup vs baseline: 1.0683x; 1.0683x over previous
#include <cuda_runtime.h>
#include <cuda_bf16.h>

// ---------------------------------------------------------------------------
// Forecaster_PONI round 16: R15 with gate3 reverted to NCO=64 (measured 283us
// vs 465us at NCO=32 — A-fill duplication dominates, so maximize NCO).
// Keeps enc3 bf16 (measured ~1.5ms win). All else identical.
// ---------------------------------------------------------------------------

__device__ __forceinline__ float lrelu_f(float v) { return v > 0.f ? v : 0.2f * v; }
__device__ __forceinline__ float sigm_f(float v)  { return 1.f / (1.f + __expf(-v)); }

__device__ __forceinline__ void mma16(float* d, const unsigned* a,
                                      unsigned b0, unsigned b1) {
    asm volatile(
        "mma.sync.aligned.m16n8k16.row.col.f32.bf16.bf16.f32 "
        "{%0,%1,%2,%3}, {%4,%5,%6,%7}, {%8,%9}, {%0,%1,%2,%3};"
        : "+f"(d[0]), "+f"(d[1]), "+f"(d[2]), "+f"(d[3])
        : "r"(a[0]), "r"(a[1]), "r"(a[2]), "r"(a[3]), "r"(b0), "r"(b1));
}

// ------------------------------ scratch buffers ----------------------------
__device__ float g_e1[160 * 16 * 96 * 96];
__device__ float g_e2[160 * 64 * 48 * 48];
__device__ float g_e3[160 * 96 * 24 * 24];
__device__ float g_c3[2][16 * 96 * 24 * 24];
__device__ float g_c2[2][16 * 64 * 48 * 48];
__device__ float g_c1[2][16 * 16 * 96 * 96];
__device__ float g_g3[16 * 192 * 24 * 24];
__device__ float g_g2[16 * 128 * 48 * 48];
__device__ float g_g1[16 * 32 * 96 * 96];
__device__ float g_o3[16 * 64 * 48 * 48];
__device__ float g_o2[16 * 16 * 96 * 96];
__device__ float g_o1[16 * 8 * 192 * 192];
__device__ float g_partD[2 * 16 * 64 * 48 * 48];

static const int NB = 16;  // batch

// ---------------------------------------------------------------------------
// bf16conv_k: 3x3 SAME conv over [x1 (C1) ++ x2 (C2)] as implicit GEMM.
// STRIDE 1: in[y+dy-1] (pad 1/1). STRIDE 2: in[2y+dy] (pad_lo=0, pad_hi=1).
// M = 64 px/block, N = NCO chans, K = CI*9 in tiles of 32, 3xBF16 hi/lo.
// MODE 1 = plain/gate conv. MODE 2 = candidate + GRU combine.
// ACT: 1 lrelu, 2 sigmoid.
// ---------------------------------------------------------------------------
template<int C1, int C2, int CO, int H, int W, int NCO, int MT, int MODE, int ACT,
         int STRIDE>
__global__ void __launch_bounds__(128)
bf16conv_k(const float* __restrict__ x1, const float* __restrict__ x2,
           const float* __restrict__ gates, const float* __restrict__ wgt,
           const float* __restrict__ bias, float* __restrict__ out)
{
    constexpr int CI   = C1 + C2;
    constexpr int K    = CI * 9;
    constexpr int KT   = 32, KTP = 34;
    constexpr int MBLK = 64 * MT;
    constexpr int NT8  = NCO / 8;
    constexpr int HIN  = H * STRIDE, WIN = W * STRIDE;
    constexpr int OFF  = (STRIDE == 1) ? 1 : 0;

    __shared__ __nv_bfloat16 sAh[MBLK][KTP], sAl[MBLK][KTP];
    __shared__ __nv_bfloat16 sBh[NCO][KTP],  sBl[NCO][KTP];

    const int n    = blockIdx.z;
    const int cob  = blockIdx.y * NCO;
    const int tile = blockIdx.x;
    const int tid  = threadIdx.x;
    const int wid  = tid >> 5;
    const int lane = tid & 31;
    const int gid  = lane >> 2;
    const int tig  = lane & 3;

    float acc[MT][NT8][4];
#pragma unroll
    for (int mt = 0; mt < MT; mt++)
#pragma unroll
        for (int j = 0; j < NT8; j++)
#pragma unroll
            for (int e = 0; e < 4; e++) acc[mt][j][e] = 0.f;

    for (int k0 = 0; k0 < K; k0 += KT) {
#pragma unroll
        for (int i = 0; i < MBLK * KT / 128; i++) {
            int idx = tid + i * 128;
            int kk  = idx & 31;
            int m   = idx >> 5;
            int k   = k0 + kk;
            int ci  = k / 9;
            int t   = k - 9 * ci;
            int dy  = t / 3, dx = t - 3 * dy;
            int p   = tile * MBLK + m;
            int y   = p / W, x = p - y * W;
            int gy  = STRIDE * y + dy - OFF, gx = STRIDE * x + dx - OFF;
            float v = 0.f;
            if ((unsigned)gy < (unsigned)HIN && (unsigned)gx < (unsigned)WIN) {
                if (ci < C1) {
                    v = x1[(((size_t)n * C1 + ci) * HIN + gy) * WIN + gx];
                } else {
                    int c2 = ci - C1;
                    v = x2[(((size_t)n * C2 + c2) * HIN + gy) * WIN + gx];
                    if (MODE == 2)
                        v *= gates[(((size_t)n * 2 * C2 + C2 + c2) * HIN + gy) * WIN + gx];
                }
            }
            __nv_bfloat16 h = __float2bfloat16(v);
            sAh[m][kk] = h;
            sAl[m][kk] = __float2bfloat16(v - __bfloat162float(h));
        }
#pragma unroll
        for (int i = 0; i < (NCO * KT + 127) / 128; i++) {
            int idx = tid + i * 128;
            if (idx < NCO * KT) {
                int kk = idx & 31;
                int co = idx >> 5;
                int k  = k0 + kk;
                int ci = k / 9;
                int t  = k - 9 * ci;
                float v = wgt[((size_t)(cob + co) * CI + ci) * 9 + t];
                __nv_bfloat16 h = __float2bfloat16(v);
                sBh[co][kk] = h;
                sBl[co][kk] = __float2bfloat16(v - __bfloat162float(h));
            }
        }
        __syncthreads();

#pragma unroll
        for (int c = 0; c < 2; c++) {
            const int ck = 16 * c;
            unsigned ah[MT][4], al[MT][4];
#pragma unroll
            for (int mt = 0; mt < MT; mt++) {
                int r0 = wid * 16 * MT + 16 * mt;
                ah[mt][0] = *(const unsigned*)&sAh[r0 + gid][ck + 2 * tig];
                ah[mt][1] = *(const unsigned*)&sAh[r0 + gid + 8][ck + 2 * tig];
                ah[mt][2] = *(const unsigned*)&sAh[r0 + gid][ck + 2 * tig + 8];
                ah[mt][3] = *(const unsigned*)&sAh[r0 + gid + 8][ck + 2 * tig + 8];
                al[mt][0] = *(const unsigned*)&sAl[r0 + gid][ck + 2 * tig];
                al[mt][1] = *(const unsigned*)&sAl[r0 + gid + 8][ck + 2 * tig];
                al[mt][2] = *(const unsigned*)&sAl[r0 + gid][ck + 2 * tig + 8];
                al[mt][3] = *(const unsigned*)&sAl[r0 + gid + 8][ck + 2 * tig + 8];
            }
#pragma unroll
            for (int j = 0; j < NT8; j++) {
                int col = 8 * j + gid;
                unsigned bh0 = *(const unsigned*)&sBh[col][ck + 2 * tig];
                unsigned bh1 = *(const unsigned*)&sBh[col][ck + 2 * tig + 8];
                unsigned bl0 = *(const unsigned*)&sBl[col][ck + 2 * tig];
                unsigned bl1 = *(const unsigned*)&sBl[col][ck + 2 * tig + 8];
#pragma unroll
                for (int mt = 0; mt < MT; mt++) {
                    mma16(acc[mt][j], ah[mt], bh0, bh1);
                    mma16(acc[mt][j], ah[mt], bl0, bl1);
                    mma16(acc[mt][j], al[mt], bh0, bh1);
                }
            }
        }
        __syncthreads();
    }

#pragma unroll
    for (int mt = 0; mt < MT; mt++) {
#pragma unroll
        for (int j = 0; j < NT8; j++) {
#pragma unroll
            for (int e = 0; e < 4; e++) {
                int r  = wid * 16 * MT + 16 * mt + gid + ((e >> 1) ? 8 : 0);
                int cc = 8 * j + 2 * tig + (e & 1);
                int p  = tile * MBLK + r;
                int y  = p / W, x = p - y * W;
                int co = cob + cc;
                float v = acc[mt][j][e] + bias[co];
                if (ACT == 1) v = lrelu_f(v);
                if (ACT == 2) v = sigm_f(v);
                size_t off = (((size_t)n * CO + co) * H + y) * W + x;
                if (MODE == 2) {
                    float z = gates[(((size_t)n * 2 * CO + co) * H + y) * W + x];
                    float h = x2[off];
                    v = (1.f - z) * h + z * v;
                }
                out[off] = v;
            }
        }
    }
}

// ---------------------------------------------------------------------------
// R2 deconv (L3): 2x2 input px -> 4x4 outputs; FUSE=0 -> raw partial write.
// ---------------------------------------------------------------------------
template<int CI, int CO, int HIN, int TY, int TX, int CICH, int COT, int SPLIT, int FUSE>
__global__ void __launch_bounds__((TY / 2) * (TX / 2))
deconv_v2(const float* __restrict__ x, const float* __restrict__ wgt,
          const float* __restrict__ bias, float* __restrict__ out)
{
    constexpr int WIN = HIN, HO = 2 * HIN, WO = 2 * HIN;
    constexpr int CIP = CI / SPLIT;
    constexpr int SH  = TY + 2, SW = TX + 2, SWP = (SW + 3) & ~3;
    constexpr int NT  = (TY / 2) * (TX / 2);
    constexpr int TILES_X = WIN / TX;

    __shared__ __align__(16) float s_in[CICH][SH][SWP];
    __shared__ __align__(16) float s_w[CICH][COT][16];

    const int zs  = blockIdx.z;
    const int n   = zs / SPLIT;
    const int sp  = zs % SPLIT;
    const int cob = blockIdx.y * COT;
    const int ty0 = (blockIdx.x / TILES_X) * TY;
    const int tx0 = (blockIdx.x % TILES_X) * TX;
    const int tid = threadIdx.x;
    const int lx  = tid % (TX / 2);
    const int ly  = tid / (TX / 2);

    float acc[COT][4][4];
#pragma unroll
    for (int c = 0; c < COT; c++)
#pragma unroll
        for (int u = 0; u < 4; u++)
#pragma unroll
            for (int v = 0; v < 4; v++) acc[c][u][v] = 0.f;

    const int ci_base = sp * CIP;
    for (int ci0 = 0; ci0 < CIP; ci0 += CICH) {
        for (int idx = tid; idx < CICH * SH * SW; idx += NT) {
            int c   = idx / (SH * SW);
            int rem = idx - c * (SH * SW);
            int iy  = rem / SW;
            int ix  = rem - iy * SW;
            int gy = ty0 + iy - 1, gx = tx0 + ix - 1;
            float v = 0.f;
            if ((unsigned)gy < (unsigned)HIN && (unsigned)gx < (unsigned)WIN)
                v = x[(((size_t)n * CI + (ci_base + ci0 + c)) * HIN + gy) * WIN + gx];
            s_in[c][iy][ix] = v;
        }
        for (int idx = tid; idx < CICH * COT * 16; idx += NT) {
            int c   = idx / (COT * 16);
            int rem = idx - c * (COT * 16);
            int co  = rem / 16;
            int k   = rem - co * 16;
            s_w[c][co][k] = wgt[((cob + co) * CI + (ci_base + ci0 + c)) * 16 + k];
        }
        __syncthreads();

#pragma unroll
        for (int c = 0; c < CICH; c++) {
            float p[4][4];
#pragma unroll
            for (int r = 0; r < 4; r++) {
                float2 a = *(const float2*)&s_in[c][2 * ly + r][2 * lx];
                float2 b = *(const float2*)&s_in[c][2 * ly + r][2 * lx + 2];
                p[r][0] = a.x; p[r][1] = a.y; p[r][2] = b.x; p[r][3] = b.y;
            }
#pragma unroll
            for (int co = 0; co < COT; co++) {
                float wk[16];
#pragma unroll
                for (int q = 0; q < 4; q++) {
                    float4 wv = *(const float4*)&s_w[c][co][4 * q];
                    wk[4 * q] = wv.x; wk[4 * q + 1] = wv.y;
                    wk[4 * q + 2] = wv.z; wk[4 * q + 3] = wv.w;
                }
#pragma unroll
                for (int u = 0; u < 4; u++)
#pragma unroll
                    for (int v = 0; v < 4; v++)
#pragma unroll
                        for (int a = 0; a < 2; a++)
#pragma unroll
                            for (int b = 0; b < 2; b++)
                                acc[co][u][v] = fmaf(
                                    p[(u >> 1) + (u & 1) + a][(v >> 1) + (v & 1) + b],
                                    wk[((u & 1) + 2 * a) * 4 + (v & 1) + 2 * b],
                                    acc[co][u][v]);
            }
        }
        __syncthreads();
    }

    const int orow0 = 2 * ty0 + 4 * ly;
    const int ocol0 = 2 * tx0 + 4 * lx;
#pragma unroll
    for (int co = 0; co < COT; co++) {
        float bv = FUSE ? bias[cob + co] : 0.f;
#pragma unroll
        for (int u = 0; u < 4; u++) {
            float4 v;
            if (FUSE) {
                v.x = lrelu_f(acc[co][u][0] + bv);
                v.y = lrelu_f(acc[co][u][1] + bv);
                v.z = lrelu_f(acc[co][u][2] + bv);
                v.w = lrelu_f(acc[co][u][3] + bv);
                *(float4*)&out[(((size_t)n * CO + cob + co) * HO + orow0 + u) * WO + ocol0] = v;
            } else {
                v.x = acc[co][u][0]; v.y = acc[co][u][1];
                v.z = acc[co][u][2]; v.w = acc[co][u][3];
                *(float4*)&out[(((size_t)(sp * NB + n) * CO + cob + co) * HO + orow0 + u) * WO + ocol0] = v;
            }
        }
    }
}

// ---------------------------------------------------------------------------
// Epilogue: sum SPLIT partials + bias; MODE 0 lrelu.
// ---------------------------------------------------------------------------
template<int CO, int HW, int SPLIT, int MODE>
__global__ void epi_k(const float* __restrict__ part, const float* __restrict__ bias,
                      const float* __restrict__ gates, const float* __restrict__ hprev,
                      float* __restrict__ out)
{
    constexpr size_t TOT = (size_t)NB * CO * HW;
    size_t i = ((size_t)blockIdx.x * blockDim.x + threadIdx.x) * 4;
    if (i >= TOT) return;
    int c   = (int)((i / HW) % CO);
    float4 s = *(const float4*)&part[i];
#pragma unroll
    for (int sp = 1; sp < SPLIT; sp++) {
        float4 q = *(const float4*)&part[(size_t)sp * TOT + i];
        s.x += q.x; s.y += q.y; s.z += q.z; s.w += q.w;
    }
    float bv = bias[c];
    s.x += bv; s.y += bv; s.z += bv; s.w += bv;
    if (MODE == 0) {
        s.x = lrelu_f(s.x); s.y = lrelu_f(s.y); s.z = lrelu_f(s.z); s.w = lrelu_f(s.w);
    } else if (MODE == 1) {
        s.x = sigm_f(s.x); s.y = sigm_f(s.y); s.z = sigm_f(s.z); s.w = sigm_f(s.w);
    } else {
        int n   = (int)(i / ((size_t)HW * CO));
        size_t pix = i % HW;
        float4 z = *(const float4*)&gates[((size_t)(n * 2 * CO + c)) * HW + pix];
        float4 h = *(const float4*)&hprev[i];
        s.x = (1.f - z.x) * h.x + z.x * lrelu_f(s.x);
        s.y = (1.f - z.y) * h.y + z.y * lrelu_f(s.y);
        s.z = (1.f - z.z) * h.z + z.z * lrelu_f(s.z);
        s.w = (1.f - z.w) * h.w + z.w * lrelu_f(s.w);
    }
    *(float4*)&out[i] = s;
}

// ---------------------------------------------------------------------------
// R1 conv3x3 (L2/L1): 2x2 px x COT per thread — measured-faster fp32 path.
// ---------------------------------------------------------------------------
template<int C1, int C2, int CO, int H, int W, int ACT, int MODE,
         int TY, int TX, int CICH, int COT>
__global__ void __launch_bounds__((TY / 2) * (TX / 2))
conv3x3_k(const float* __restrict__ x1, const float* __restrict__ x2,
          const float* __restrict__ gates, const float* __restrict__ wgt,
          const float* __restrict__ bias, float* __restrict__ out)
{
    constexpr int CI = C1 + C2;
    constexpr int SH = TY + 2, SW = TX + 2;
    constexpr int NT = (TY / 2) * (TX / 2);
    constexpr int TILES_X = (W + TX - 1) / TX;
    __shared__ float s_in[CICH][SH][SW];
    __shared__ float s_w[CICH][COT][9];

    const int n   = blockIdx.z;
    const int cob = blockIdx.y * COT;
    const int ty0 = (blockIdx.x / TILES_X) * TY;
    const int tx0 = (blockIdx.x % TILES_X) * TX;
    const int tid = threadIdx.x;
    const int lx  = tid % (TX / 2);
    const int ly  = tid / (TX / 2);

    float acc[COT][2][2];
#pragma unroll
    for (int c = 0; c < COT; c++) {
        acc[c][0][0] = acc[c][0][1] = acc[c][1][0] = acc[c][1][1] = 0.f;
    }

    for (int ci0 = 0; ci0 < CI; ci0 += CICH) {
        for (int idx = tid; idx < CICH * SH * SW; idx += NT) {
            int c   = idx / (SH * SW);
            int rem = idx - c * (SH * SW);
            int iy  = rem / SW;
            int ix  = rem - iy * SW;
            int gy = ty0 + iy - 1, gx = tx0 + ix - 1;
            int ci = ci0 + c;
            float v = 0.f;
            if ((unsigned)gy < (unsigned)H && (unsigned)gx < (unsigned)W) {
                if (ci < C1) {
                    v = x1[(((size_t)n * C1 + ci) * H + gy) * W + gx];
                } else {
                    int c2 = ci - C1;
                    v = x2[(((size_t)n * C2 + c2) * H + gy) * W + gx];
                    if (MODE == 2)
                        v *= gates[(((size_t)n * 2 * C2 + C2 + c2) * H + gy) * W + gx];
                }
            }
            s_in[c][iy][ix] = v;
        }
        for (int idx = tid; idx < CICH * COT * 9; idx += NT) {
            int c   = idx / (COT * 9);
            int rem = idx - c * (COT * 9);
            int co  = rem / 9;
            int k   = rem - co * 9;
            s_w[c][co][k] = wgt[((cob + co) * CI + (ci0 + c)) * 9 + k];
        }
        __syncthreads();

        for (int c = 0; c < CICH; c++) {
            float p[4][4];
#pragma unroll
            for (int i = 0; i < 4; i++)
#pragma unroll
                for (int j = 0; j < 4; j++)
                    p[i][j] = s_in[c][2 * ly + i][2 * lx + j];
#pragma unroll
            for (int co = 0; co < COT; co++) {
#pragma unroll
                for (int ky = 0; ky < 3; ky++)
#pragma unroll
                    for (int kx = 0; kx < 3; kx++) {
                        float wv = s_w[c][co][ky * 3 + kx];
                        acc[co][0][0] = fmaf(p[ky][kx],         wv, acc[co][0][0]);
                        acc[co][0][1] = fmaf(p[ky][kx + 1],     wv, acc[co][0][1]);
                        acc[co][1][0] = fmaf(p[ky + 1][kx],     wv, acc[co][1][0]);
                        acc[co][1][1] = fmaf(p[ky + 1][kx + 1], wv, acc[co][1][1]);
                    }
            }
        }
        __syncthreads();
    }

    const int oy = ty0 + 2 * ly, ox = tx0 + 2 * lx;
#pragma unroll
    for (int co = 0; co < COT; co++) {
        float bv = bias[cob + co];
#pragma unroll
        for (int i = 0; i < 2; i++)
#pragma unroll
            for (int j = 0; j < 2; j++) {
                int y = oy + i, x = ox + j;
                if (y < H && x < W) {
                    float v = acc[co][i][j] + bv;
                    if (ACT == 1) v = lrelu_f(v);
                    if (ACT == 2) v = sigm_f(v);
                    size_t off = (((size_t)n * CO + cob + co) * H + y) * W + x;
                    if (MODE == 2) {
                        float z = gates[(((size_t)n * 2 * CO + cob + co) * H + y) * W + x];
                        float h = x2[off];
                        v = (1.f - z) * h + z * v;
                    }
                    out[off] = v;
                }
            }
    }
}

// ---------------------------------------------------------------------------
// R1 deconv (L2/L1): fused lrelu.
// ---------------------------------------------------------------------------
template<int CI, int CO, int HIN, int TY, int TX, int CICH, int COT>
__global__ void __launch_bounds__(TY * TX)
deconv4x4_k(const float* __restrict__ x, const float* __restrict__ wgt,
            const float* __restrict__ bias, float* __restrict__ out)
{
    constexpr int WIN = HIN, HO = 2 * HIN, WO = 2 * HIN;
    constexpr int SH = TY + 2, SW = TX + 2;
    constexpr int NT = TY * TX;
    constexpr int TILES_X = (WIN + TX - 1) / TX;
    __shared__ float s_in[CICH][SH][SW];
    __shared__ float s_w[CICH][COT][16];

    const int n   = blockIdx.z;
    const int cob = blockIdx.y * COT;
    const int ty0 = (blockIdx.x / TILES_X) * TY;
    const int tx0 = (blockIdx.x % TILES_X) * TX;
    const int tid = threadIdx.x;
    const int lx  = tid % TX;
    const int ly  = tid / TX;

    float acc[COT][2][2];
#pragma unroll
    for (int c = 0; c < COT; c++) {
        acc[c][0][0] = acc[c][0][1] = acc[c][1][0] = acc[c][1][1] = 0.f;
    }

    for (int ci0 = 0; ci0 < CI; ci0 += CICH) {
        for (int idx = tid; idx < CICH * SH * SW; idx += NT) {
            int c   = idx / (SH * SW);
            int rem = idx - c * (SH * SW);
            int iy  = rem / SW;
            int ix  = rem - iy * SW;
            int gy = ty0 + iy - 1, gx = tx0 + ix - 1;
            float v = 0.f;
            if ((unsigned)gy < (unsigned)HIN && (unsigned)gx < (unsigned)WIN)
                v = x[(((size_t)n * CI + (ci0 + c)) * HIN + gy) * WIN + gx];
            s_in[c][iy][ix] = v;
        }
        for (int idx = tid; idx < CICH * COT * 16; idx += NT) {
            int c   = idx / (COT * 16);
            int rem = idx - c * (COT * 16);
            int co  = rem / 16;
            int k   = rem - co * 16;
            s_w[c][co][k] = wgt[((cob + co) * CI + (ci0 + c)) * 16 + k];
        }
        __syncthreads();

        for (int c = 0; c < CICH; c++) {
            float p[3][3];
#pragma unroll
            for (int r = 0; r < 3; r++)
#pragma unroll
                for (int cc = 0; cc < 3; cc++)
                    p[r][cc] = s_in[c][ly + r][lx + cc];
#pragma unroll
            for (int co = 0; co < COT; co++) {
#pragma unroll
                for (int dy = 0; dy < 2; dy++)
#pragma unroll
                    for (int dx = 0; dx < 2; dx++)
#pragma unroll
                        for (int a = 0; a < 2; a++)
#pragma unroll
                            for (int b = 0; b < 2; b++)
                                acc[co][dy][dx] =
                                    fmaf(p[a + dy][b + dx],
                                         s_w[c][co][(dy + 2 * a) * 4 + (dx + 2 * b)],
                                         acc[co][dy][dx]);
            }
        }
        __syncthreads();
    }

    const int iy = ty0 + ly, ix = tx0 + lx;
    if (iy < HIN && ix < WIN) {
#pragma unroll
        for (int co = 0; co < COT; co++) {
            float bv = bias[cob + co];
#pragma unroll
            for (int dy = 0; dy < 2; dy++)
#pragma unroll
                for (int dx = 0; dx < 2; dx++) {
                    float v = lrelu_f(acc[co][dy][dx] + bv);
                    out[(((size_t)n * CO + cob + co) * HO + 2 * iy + dy) * WO + 2 * ix + dx] = v;
                }
        }
    }
}

// ---------------------------------------------------------------------------
// Encoder: 3x3 stride-2 SAME conv (enc1/enc2). REMAP folds [B,T]->[T,B].
// ---------------------------------------------------------------------------
template<int CI, int CO, int HIN, bool REMAP, int TY, int TX, int CICH, int COT>
__global__ void __launch_bounds__(TY * TX)
conv3x3s2_k(const float* __restrict__ x, const float* __restrict__ wgt,
            const float* __restrict__ bias, float* __restrict__ out)
{
    constexpr int WIN = HIN, HO = HIN / 2, WO = HIN / 2;
    constexpr int SH = 2 * TY + 1, SW = 2 * TX + 1;
    constexpr int NT = TY * TX;
    constexpr int TILES_X = (WO + TX - 1) / TX;
    __shared__ float s_in[CICH][SH][SW];
    __shared__ float s_w[CICH][COT][9];

    const int n   = blockIdx.z;
    const int cob = blockIdx.y * COT;
    const int ty0 = (blockIdx.x / TILES_X) * TY;
    const int tx0 = (blockIdx.x % TILES_X) * TX;
    const int tid = threadIdx.x;
    const int lx  = tid % TX;
    const int ly  = tid / TX;

    float acc[COT];
#pragma unroll
    for (int c = 0; c < COT; c++) acc[c] = 0.f;

    for (int ci0 = 0; ci0 < CI; ci0 += CICH) {
        for (int idx = tid; idx < CICH * SH * SW; idx += NT) {
            int c   = idx / (SH * SW);
            int rem = idx - c * (SH * SW);
            int iy  = rem / SW;
            int ix  = rem - iy * SW;
            int gy = 2 * ty0 + iy, gx = 2 * tx0 + ix;
            int ci = ci0 + c;
            float v = 0.f;
            if (gy < HIN && gx < WIN) {
                int frame = REMAP ? ((n % 16) * 10 + n / 16) : n;
                v = x[(((size_t)frame * CI + ci) * HIN + gy) * WIN + gx];
            }
            s_in[c][iy][ix] = v;
        }
        for (int idx = tid; idx < CICH * COT * 9; idx += NT) {
            int c   = idx / (COT * 9);
            int rem = idx - c * (COT * 9);
            int co  = rem / 9;
            int k   = rem - co * 9;
            s_w[c][co][k] = wgt[((cob + co) * CI + (ci0 + c)) * 9 + k];
        }
        __syncthreads();

        for (int c = 0; c < CICH; c++) {
            float p[3][3];
#pragma unroll
            for (int r = 0; r < 3; r++)
#pragma unroll
                for (int cc = 0; cc < 3; cc++)
                    p[r][cc] = s_in[c][2 * ly + r][2 * lx + cc];
#pragma unroll
            for (int co = 0; co < COT; co++) {
#pragma unroll
                for (int k = 0; k < 9; k++)
                    acc[co] = fmaf(p[k / 3][k % 3], s_w[c][co][k], acc[co]);
            }
        }
        __syncthreads();
    }

    const int oy = ty0 + ly, ox = tx0 + lx;
    if (oy < HO && ox < WO) {
#pragma unroll
        for (int co = 0; co < COT; co++) {
            float v = lrelu_f(acc[co] + bias[cob + co]);
            out[(((size_t)n * CO + cob + co) * HO + oy) * WO + ox] = v;
        }
    }
}

// ---------------------------------------------------------------------------
// Head: 3x3 conv, 8 -> 1 channels, 192x192.
// ---------------------------------------------------------------------------
__global__ void head_k(const float* __restrict__ x, const float* __restrict__ w,
                       const float* __restrict__ b, float* __restrict__ out)
{
    __shared__ float sw[72];
    __shared__ float sb;
    if (threadIdx.x < 72) sw[threadIdx.x] = w[threadIdx.x];
    if (threadIdx.x == 0) sb = b[0];
    __syncthreads();

    const int HW = 192 * 192;
    int idx = blockIdx.x * blockDim.x + threadIdx.x;
    if (idx >= 16 * HW) return;
    int n   = idx / HW;
    int rem = idx - n * HW;
    int y   = rem / 192;
    int xq  = rem - y * 192;

    float acc = sb;
#pragma unroll
    for (int ci = 0; ci < 8; ci++) {
        const float* xp = x + (size_t)(n * 8 + ci) * HW;
#pragma unroll
        for (int ky = 0; ky < 3; ky++) {
            int yy = y + ky - 1;
            if ((unsigned)yy >= 192u) continue;
#pragma unroll
            for (int kx = 0; kx < 3; kx++) {
                int xx = xq + kx - 1;
                if ((unsigned)xx >= 192u) continue;
                acc = fmaf(xp[yy * 192 + xx], sw[ci * 9 + ky * 3 + kx], acc);
            }
        }
    }
    out[idx] = acc;
}

// ---------------------------------------------------------------------------
// stream/event context — identical object count to the passing R8/R10 ctx.
// ---------------------------------------------------------------------------
struct PipeCtx {
    cudaStream_t sA, sB, sC;
    cudaEvent_t  fork, jA, jB, jC;
    cudaEvent_t  eA[10];    // A: c3n(t) ready
    cudaEvent_t  eBc3[10];  // B: deconv3(t) done reading c3n(t)
    cudaEvent_t  eB[10];    // B: c2n(t) ready
    cudaEvent_t  eCc2[10];  // C: deconv2(t) done reading c2n(t)
};

static PipeCtx* get_ctx() {
    static PipeCtx* c = nullptr;
    if (!c) {
        c = new PipeCtx;
        cudaStreamCreateWithFlags(&c->sA, cudaStreamNonBlocking);
        cudaStreamCreateWithFlags(&c->sB, cudaStreamNonBlocking);
        cudaStreamCreateWithFlags(&c->sC, cudaStreamNonBlocking);
        cudaEventCreateWithFlags(&c->fork, cudaEventDisableTiming);
        cudaEventCreateWithFlags(&c->jA,   cudaEventDisableTiming);
        cudaEventCreateWithFlags(&c->jB,   cudaEventDisableTiming);
        cudaEventCreateWithFlags(&c->jC,   cudaEventDisableTiming);
        for (int t = 0; t < 10; t++) {
            cudaEventCreateWithFlags(&c->eA[t],   cudaEventDisableTiming);
            cudaEventCreateWithFlags(&c->eBc3[t], cudaEventDisableTiming);
            cudaEventCreateWithFlags(&c->eB[t],   cudaEventDisableTiming);
            cudaEventCreateWithFlags(&c->eCc2[t], cudaEventDisableTiming);
        }
    }
    return c;
}

// ---------------------------------------------------------------------------
// host
// ---------------------------------------------------------------------------
extern "C" void kernel_launch(void* const* d_in, const int* in_sizes, int n_in,
                              void* d_out, int out_size)
{
    const float* h1     = (const float*)d_in[0];
    const float* h2     = (const float*)d_in[1];
    const float* h3     = (const float*)d_in[2];
    const float* y_add  = (const float*)d_in[3];
    const float* enc_w1 = (const float*)d_in[4];
    const float* enc_b1 = (const float*)d_in[5];
    const float* enc_w2 = (const float*)d_in[6];
    const float* enc_b2 = (const float*)d_in[7];
    const float* enc_w3 = (const float*)d_in[8];
    const float* enc_b3 = (const float*)d_in[9];
    const float* g3wg   = (const float*)d_in[10];
    const float* g3bg   = (const float*)d_in[11];
    const float* g3wc   = (const float*)d_in[12];
    const float* g3bc   = (const float*)d_in[13];
    const float* g2wg   = (const float*)d_in[14];
    const float* g2bg   = (const float*)d_in[15];
    const float* g2wc   = (const float*)d_in[16];
    const float* g2bc   = (const float*)d_in[17];
    const float* g1wg   = (const float*)d_in[18];
    const float* g1bg   = (const float*)d_in[19];
    const float* g1wc   = (const float*)d_in[20];
    const float* g1bc   = (const float*)d_in[21];
    const float* s3w    = (const float*)d_in[22];
    const float* s3b    = (const float*)d_in[23];
    const float* s2w    = (const float*)d_in[24];
    const float* s2b    = (const float*)d_in[25];
    const float* s1w    = (const float*)d_in[26];
    const float* s1b    = (const float*)d_in[27];
    const float* hw     = (const float*)d_in[28];
    const float* hb     = (const float*)d_in[29];
    float* out = (float*)d_out;

    float *e1, *e2, *e3, *c3b, *c2b, *c1b, *gg3, *gg2, *gg1, *o3, *o2, *o1, *partD;
    cudaGetSymbolAddress((void**)&e1, g_e1);
    cudaGetSymbolAddress((void**)&e2, g_e2);
    cudaGetSymbolAddress((void**)&e3, g_e3);
    cudaGetSymbolAddress((void**)&c3b, g_c3);
    cudaGetSymbolAddress((void**)&c2b, g_c2);
    cudaGetSymbolAddress((void**)&c1b, g_c1);
    cudaGetSymbolAddress((void**)&gg3, g_g3);
    cudaGetSymbolAddress((void**)&gg2, g_g2);
    cudaGetSymbolAddress((void**)&gg1, g_g1);
    cudaGetSymbolAddress((void**)&o3, g_o3);
    cudaGetSymbolAddress((void**)&o2, g_o2);
    cudaGetSymbolAddress((void**)&o1, g_o1);
    cudaGetSymbolAddress((void**)&partD, g_partD);

    PipeCtx* c = get_ctx();
    cudaStream_t sA = c->sA, sB = c->sB, sC = c->sC;

    const size_t SZ3 = (size_t)16 * 96 * 24 * 24;
    const size_t SZ2 = (size_t)16 * 64 * 48 * 48;
    const size_t SZ1 = (size_t)16 * 16 * 96 * 96;

    // -------- encoder on the capture-origin stream --------------------------
    conv3x3s2_k<1, 16, 192, true, 16, 16, 1, 16><<<dim3(36, 1, 160), 256>>>(
        y_add, enc_w1, enc_b1, e1);
    conv3x3s2_k<16, 64, 96, false, 16, 16, 8, 8><<<dim3(9, 8, 160), 256>>>(
        e1, enc_w2, enc_b2, e2);
    // enc3 on tensor cores: stride-2 bf16 implicit GEMM (measured win)
    bf16conv_k<64, 0, 96, 24, 24, 32, 1, 1, 1, 2>
        <<<dim3(9, 3, 160), 128>>>(e2, e2, nullptr, enc_w3, enc_b3, e3);

    cudaMemcpyAsync(c3b, h3, SZ3 * sizeof(float), cudaMemcpyDeviceToDevice);
    cudaMemcpyAsync(c2b, h2, SZ2 * sizeof(float), cudaMemcpyDeviceToDevice);
    cudaMemcpyAsync(c1b, h1, SZ1 * sizeof(float), cudaMemcpyDeviceToDevice);

    // -------- fork into 3 pipeline streams ----------------------------------
    cudaEventRecord(c->fork, 0);
    cudaStreamWaitEvent(sA, c->fork, 0);
    cudaStreamWaitEvent(sB, c->fork, 0);
    cudaStreamWaitEvent(sC, c->fork, 0);

    for (int t = 0; t < 10; t++) {
        const float* x3 = e3 + (size_t)t * 16 * 96 * 24 * 24;
        float* c3c = c3b + (size_t)(t & 1) * SZ3;
        float* c3n = c3b + (size_t)((t + 1) & 1) * SZ3;
        float* c2c = c2b + (size_t)(t & 1) * SZ2;
        float* c2n = c2b + (size_t)((t + 1) & 1) * SZ2;
        float* c1c = c1b + (size_t)(t & 1) * SZ1;
        float* c1n = c1b + (size_t)((t + 1) & 1) * SZ1;

        // ===== stream A: L3 GRU recurrence (bf16, gate3 back to NCO=64) =====
        bf16conv_k<96, 96, 192, 24, 24, 64, 1, 1, 2, 1>
            <<<dim3(9, 3, 16), 128, 0, sA>>>(x3, c3c, nullptr, g3wg, g3bg, gg3);
        if (t >= 2) cudaStreamWaitEvent(sA, c->eBc3[t - 2], 0);
        bf16conv_k<96, 96, 96, 24, 24, 32, 1, 2, 1, 1>
            <<<dim3(9, 3, 16), 128, 0, sA>>>(x3, c3c, gg3, g3wc, g3bc, c3n);
        cudaEventRecord(c->eA[t], sA);                           // c3n(t) ready

        // ===== stream B: deconv3 -> o3, then L2 GRU (fp32, R10 configs) =====
        cudaStreamWaitEvent(sB, c->eA[t], 0);
        deconv_v2<96, 64, 24, 24, 24, 8, 4, 2, 0>
            <<<dim3(1, 16, 32), 144, 0, sB>>>(c3n, s3w, s3b, partD);
        cudaEventRecord(c->eBc3[t], sB);                         // done reading c3n(t)
        epi_k<64, 2304, 2, 0><<<2304, 256, 0, sB>>>(partD, s3b, nullptr, nullptr, o3);
        conv3x3_k<64, 64, 128, 48, 48, 2, 1, 16, 48, 8, 8>
            <<<dim3(3, 16, 16), 192, 0, sB>>>(o3, c2c, nullptr, g2wg, g2bg, gg2);
        if (t >= 2) cudaStreamWaitEvent(sB, c->eCc2[t - 2], 0);
        conv3x3_k<64, 64, 64, 48, 48, 1, 2, 16, 48, 8, 8>
            <<<dim3(3, 8, 16), 192, 0, sB>>>(o3, c2c, gg2, g2wc, g2bc, c2n);
        cudaEventRecord(c->eB[t], sB);                           // c2n(t) ready

        // ===== stream C: deconv2 -> o2, L1 GRU (fp32), deconv1, head =====
        cudaStreamWaitEvent(sC, c->eB[t], 0);
        deconv4x4_k<64, 16, 48, 16, 48, 8, 4>
            <<<dim3(3, 4, 16), 768, 0, sC>>>(c2n, s2w, s2b, o2);
        cudaEventRecord(c->eCc2[t], sC);                         // done reading c2n(t)
        conv3x3_k<16, 16, 32, 96, 96, 2, 1, 16, 48, 8, 8>
            <<<dim3(12, 4, 16), 192, 0, sC>>>(o2, c1c, nullptr, g1wg, g1bg, gg1);
        conv3x3_k<16, 16, 16, 96, 96, 1, 2, 16, 48, 8, 8>
            <<<dim3(12, 2, 16), 192, 0, sC>>>(o2, c1c, gg1, g1wc, g1bc, c1n);
        deconv4x4_k<16, 8, 96, 16, 48, 8, 8>
            <<<dim3(12, 1, 16), 768, 0, sC>>>(c1n, s1w, s1b, o1);
        head_k<<<dim3((16 * 192 * 192 + 255) / 256), 256, 0, sC>>>(
            o1, hw, hb, out + (size_t)t * 16 * 192 * 192);
    }

    // -------- join all streams back to the capture-origin stream ------------
    cudaEventRecord(c->jA, sA);
    cudaEventRecord(c->jB, sB);
    cudaEventRecord(c->jC, sC);
    cudaStreamWaitEvent(0, c->jA, 0);
    cudaStreamWaitEvent(0, c->jB, 0);
    cudaStreamWaitEvent(0, c->jC, 0);
}